// round 1
// baseline (speedup 1.0000x reference)
#include <cuda_runtime.h>
#include <math.h>

// Problem constants
#define BATCH 8
#define SEQ   1024
#define EMB   768
#define NHEAD 12
#define HD    64
#define M_ROWS (BATCH * SEQ)        // 8192
#define QKV_N  (3 * EMB)            // 2304

// Scratch (device globals — no allocations allowed)
__device__ float g_Q[BATCH * NHEAD * SEQ * HD];   // [b,h,t,d]
__device__ float g_K[BATCH * NHEAD * SEQ * HD];
__device__ float g_V[BATCH * NHEAD * SEQ * HD];
__device__ float g_Y[M_ROWS * EMB];               // attention output, [b*t, c]

// ---------------------------------------------------------------------------
// GEMM 1: qkv = x @ W_attn + b_attn, scattered into g_Q/g_K/g_V head-major.
// A: [8192, 768] row-major, W: [768, 2304] row-major.
// Tile: BM=64, BN=64, BK=16, 256 threads, 4x4 register block per thread.
// ---------------------------------------------------------------------------
#define BM 64
#define BN 64
#define BK 16

__global__ __launch_bounds__(256) void gemm_qkv_kernel(
    const float* __restrict__ A, const float* __restrict__ W,
    const float* __restrict__ bias)
{
    __shared__ float As[BK][BM];
    __shared__ float Bs[BK][BN];

    const int tid = threadIdx.x;
    const int m0 = blockIdx.y * BM;
    const int n0 = blockIdx.x * BN;
    const int ty = tid >> 4;          // 0..15
    const int tx = tid & 15;          // 0..15

    // load mapping
    const int arow = tid >> 2;        // 0..63
    const int acol = (tid & 3) * 4;   // 0,4,8,12
    const int brow = tid >> 4;        // 0..15
    const int bcol = (tid & 15) * 4;  // 0..60

    float acc[4][4];
#pragma unroll
    for (int i = 0; i < 4; i++)
#pragma unroll
        for (int j = 0; j < 4; j++) acc[i][j] = 0.f;

    for (int k0 = 0; k0 < EMB; k0 += BK) {
        float4 av = *(const float4*)(A + (size_t)(m0 + arow) * EMB + k0 + acol);
        As[acol + 0][arow] = av.x;
        As[acol + 1][arow] = av.y;
        As[acol + 2][arow] = av.z;
        As[acol + 3][arow] = av.w;
        *(float4*)&Bs[brow][bcol] =
            *(const float4*)(W + (size_t)(k0 + brow) * QKV_N + n0 + bcol);
        __syncthreads();

#pragma unroll
        for (int kk = 0; kk < BK; kk++) {
            float4 a4 = *(const float4*)&As[kk][ty * 4];
            float4 b4 = *(const float4*)&Bs[kk][tx * 4];
            float a[4] = {a4.x, a4.y, a4.z, a4.w};
            float b[4] = {b4.x, b4.y, b4.z, b4.w};
#pragma unroll
            for (int i = 0; i < 4; i++)
#pragma unroll
                for (int j = 0; j < 4; j++) acc[i][j] += a[i] * b[j];
        }
        __syncthreads();
    }

    // epilogue: bias + scatter into Q/K/V [b,h,t,d]
#pragma unroll
    for (int i = 0; i < 4; i++) {
        const int m = m0 + ty * 4 + i;
        const int b = m >> 10;          // m / 1024
        const int t = m & 1023;
#pragma unroll
        for (int j = 0; j < 4; j++) {
            const int n = n0 + tx * 4 + j;
            const float v = acc[i][j] + bias[n];
            const int which = n / EMB;      // 0=q 1=k 2=v
            const int c = n - which * EMB;
            const int h = c >> 6;
            const int d = c & 63;
            float* dst = (which == 0) ? g_Q : (which == 1) ? g_K : g_V;
            dst[(((size_t)b * NHEAD + h) * SEQ + t) * HD + d] = v;
        }
    }
}

// ---------------------------------------------------------------------------
// Causal flash attention. One thread per query row; 128 rows per block.
// K/V staged in SMEM in 64-row tiles; all inner-loop SMEM reads broadcast.
// ---------------------------------------------------------------------------
#define TQ 128
#define TS 64

__global__ __launch_bounds__(128) void attn_kernel()
{
    __shared__ float Ks[TS][HD];
    __shared__ float Vs[TS][HD];

    const int bh = blockIdx.y;                       // 0..95
    const int r = blockIdx.x * TQ + threadIdx.x;     // query row
    const float scale = 0.125f;                      // 1/sqrt(64)

    const float* Qp = g_Q + ((size_t)bh * SEQ + r) * HD;
    float q[HD];
#pragma unroll
    for (int d = 0; d < HD; d += 4) {
        float4 v4 = *(const float4*)(Qp + d);
        q[d] = v4.x; q[d + 1] = v4.y; q[d + 2] = v4.z; q[d + 3] = v4.w;
    }

    float o[HD];
#pragma unroll
    for (int d = 0; d < HD; d++) o[d] = 0.f;
    float mrow = -1e30f;
    float l = 0.f;

    const int rmax = blockIdx.x * TQ + TQ - 1;
    const int kend = rmax + 1;                        // keys needed by this block

    const float* Kbase = g_K + (size_t)bh * SEQ * HD;
    const float* Vbase = g_V + (size_t)bh * SEQ * HD;

    for (int t0 = 0; t0 < kend; t0 += TS) {
        __syncthreads();
        // cooperative tile load: TS*HD/4 = 1024 float4 per array, 8 per thread
        const float4* Kp = (const float4*)(Kbase + (size_t)t0 * HD);
        const float4* Vp = (const float4*)(Vbase + (size_t)t0 * HD);
        float4* Kss = (float4*)&Ks[0][0];
        float4* Vss = (float4*)&Vs[0][0];
#pragma unroll
        for (int it = 0; it < 8; it++) {
            int i = threadIdx.x + it * 128;
            Kss[i] = Kp[i];
            Vss[i] = Vp[i];
        }
        __syncthreads();

        // scores for this tile
        float s[TS];
        for (int j = 0; j < TS; j++) {
            const float4* kr = (const float4*)&Ks[j][0];
            float a0 = 0.f, a1 = 0.f, a2 = 0.f, a3 = 0.f;
#pragma unroll
            for (int d = 0; d < HD / 4; d++) {
                float4 kv = kr[d];
                a0 += q[4 * d + 0] * kv.x;
                a1 += q[4 * d + 1] * kv.y;
                a2 += q[4 * d + 2] * kv.z;
                a3 += q[4 * d + 3] * kv.w;
            }
            float val = (a0 + a1 + a2 + a3) * scale;
            s[j] = (t0 + j <= r) ? val : -1e30f;
        }

        // tile max + online softmax rescale
        float tmax = -1e30f;
        for (int j = 0; j < TS; j++) tmax = fmaxf(tmax, s[j]);
        float mnew = fmaxf(mrow, tmax);
        float corr = __expf(mrow - mnew);
        l *= corr;
#pragma unroll
        for (int d = 0; d < HD; d++) o[d] *= corr;
        mrow = mnew;

        for (int j = 0; j < TS; j++) {
            float p = __expf(s[j] - mnew);
            l += p;
            const float4* vr = (const float4*)&Vs[j][0];
#pragma unroll
            for (int d = 0; d < HD / 4; d++) {
                float4 vv = vr[d];
                o[4 * d + 0] += p * vv.x;
                o[4 * d + 1] += p * vv.y;
                o[4 * d + 2] += p * vv.z;
                o[4 * d + 3] += p * vv.w;
            }
        }
    }

    // write back to [b, t, h*64 + d]
    const float inv = 1.f / l;
    const int b = bh / NHEAD;
    const int h = bh - b * NHEAD;
    float* yp = g_Y + ((size_t)(b * SEQ + r)) * EMB + h * HD;
#pragma unroll
    for (int d = 0; d < HD; d += 4) {
        float4 v4;
        v4.x = o[d] * inv; v4.y = o[d + 1] * inv;
        v4.z = o[d + 2] * inv; v4.w = o[d + 3] * inv;
        *(float4*)(yp + d) = v4;
    }
}

// ---------------------------------------------------------------------------
// GEMM 2: out = y @ W_proj + b_proj.  [8192,768] x [768,768]
// ---------------------------------------------------------------------------
__global__ __launch_bounds__(256) void gemm_proj_kernel(
    const float* __restrict__ W, const float* __restrict__ bias,
    float* __restrict__ out)
{
    __shared__ float As[BK][BM];
    __shared__ float Bs[BK][BN];

    const int tid = threadIdx.x;
    const int m0 = blockIdx.y * BM;
    const int n0 = blockIdx.x * BN;
    const int ty = tid >> 4;
    const int tx = tid & 15;

    const int arow = tid >> 2;
    const int acol = (tid & 3) * 4;
    const int brow = tid >> 4;
    const int bcol = (tid & 15) * 4;

    float acc[4][4];
#pragma unroll
    for (int i = 0; i < 4; i++)
#pragma unroll
        for (int j = 0; j < 4; j++) acc[i][j] = 0.f;

    for (int k0 = 0; k0 < EMB; k0 += BK) {
        float4 av = *(const float4*)(g_Y + (size_t)(m0 + arow) * EMB + k0 + acol);
        As[acol + 0][arow] = av.x;
        As[acol + 1][arow] = av.y;
        As[acol + 2][arow] = av.z;
        As[acol + 3][arow] = av.w;
        *(float4*)&Bs[brow][bcol] =
            *(const float4*)(W + (size_t)(k0 + brow) * EMB + n0 + bcol);
        __syncthreads();

#pragma unroll
        for (int kk = 0; kk < BK; kk++) {
            float4 a4 = *(const float4*)&As[kk][ty * 4];
            float4 b4 = *(const float4*)&Bs[kk][tx * 4];
            float a[4] = {a4.x, a4.y, a4.z, a4.w};
            float b[4] = {b4.x, b4.y, b4.z, b4.w};
#pragma unroll
            for (int i = 0; i < 4; i++)
#pragma unroll
                for (int j = 0; j < 4; j++) acc[i][j] += a[i] * b[j];
        }
        __syncthreads();
    }

#pragma unroll
    for (int i = 0; i < 4; i++) {
        const int m = m0 + ty * 4 + i;
#pragma unroll
        for (int j = 0; j < 4; j += 4) {
            const int n = n0 + tx * 4;
            float4 v4;
            v4.x = acc[i][0] + bias[n + 0];
            v4.y = acc[i][1] + bias[n + 1];
            v4.z = acc[i][2] + bias[n + 2];
            v4.w = acc[i][3] + bias[n + 3];
            *(float4*)(out + (size_t)m * EMB + n) = v4;
        }
    }
}

// ---------------------------------------------------------------------------
extern "C" void kernel_launch(void* const* d_in, const int* in_sizes, int n_in,
                              void* d_out, int out_size)
{
    const float* x      = (const float*)d_in[0];
    const float* W_attn = (const float*)d_in[1];
    const float* b_attn = (const float*)d_in[2];
    const float* W_proj = (const float*)d_in[3];
    const float* b_proj = (const float*)d_in[4];
    float* out = (float*)d_out;

    (void)in_sizes; (void)n_in; (void)out_size;

    dim3 g1(QKV_N / BN, M_ROWS / BM);      // (36, 128)
    gemm_qkv_kernel<<<g1, 256>>>(x, W_attn, b_attn);

    dim3 g2(SEQ / TQ, BATCH * NHEAD);      // (8, 96)
    attn_kernel<<<g2, 128>>>();

    dim3 g3(EMB / BN, M_ROWS / BM);        // (12, 128)
    gemm_proj_kernel<<<g3, 256>>>(W_proj, b_proj, out);
}

// round 2
// speedup vs baseline: 1.7941x; 1.7941x over previous
#include <cuda_runtime.h>
#include <math.h>
#include <stdint.h>

// Problem constants
#define BATCH 8
#define SEQ   1024
#define EMB   768
#define NHEAD 12
#define HD    64
#define M_ROWS (BATCH * SEQ)        // 8192
#define QKV_N  (3 * EMB)            // 2304

// Scratch (device globals — no allocations allowed)
__device__ float g_Q[BATCH * NHEAD * SEQ * HD];   // [b,h,t,d]
__device__ float g_K[BATCH * NHEAD * SEQ * HD];
__device__ float g_V[BATCH * NHEAD * SEQ * HD];
__device__ float g_Y[M_ROWS * EMB];               // attention output, [b*t, c]

// ---------------------------------------------------------------------------
// tf32 helpers
// ---------------------------------------------------------------------------
__device__ __forceinline__ uint32_t f2tf32(float f) {
    uint32_t u;
    asm("cvt.rna.tf32.f32 %0, %1;" : "=r"(u) : "f"(f));
    return u;
}

__device__ __forceinline__ void mma_tf32(float c[4],
                                         uint32_t a0, uint32_t a1, uint32_t a2, uint32_t a3,
                                         uint32_t b0, uint32_t b1) {
    asm volatile(
        "mma.sync.aligned.m16n8k8.row.col.f32.tf32.tf32.f32 "
        "{%0,%1,%2,%3}, {%4,%5,%6,%7}, {%8,%9}, {%0,%1,%2,%3};\n"
        : "+f"(c[0]), "+f"(c[1]), "+f"(c[2]), "+f"(c[3])
        : "r"(a0), "r"(a1), "r"(a2), "r"(a3), "r"(b0), "r"(b1));
}

// ---------------------------------------------------------------------------
// tf32 tensor-core GEMM: C[M, NDIM] = A[M,768] @ B[768,NDIM] + bias
// Block tile 128x128, BK=16, 256 threads = 8 warps (warp tile 32x64).
// MODE 0: QKV — scatter into g_Q/g_K/g_V head-major.
// MODE 1: proj — A is g_Y, write out = y @ W_proj + bias.
// ---------------------------------------------------------------------------
#define GBK 16
#define SPAD 136   // 128 + 8: conflict-free fragment loads

template<int NDIM, int MODE>
__global__ __launch_bounds__(256, 2) void gemm_tf32_kernel(
    const float* __restrict__ Ain, const float* __restrict__ B,
    const float* __restrict__ bias, float* __restrict__ out)
{
    __shared__ uint32_t As[GBK][SPAD];   // [k][m]
    __shared__ uint32_t Bs[GBK][SPAD];   // [k][n]

    const float* A = (MODE == 1) ? g_Y : Ain;

    const int tid = threadIdx.x;
    const int m0 = blockIdx.y * 128;
    const int n0 = blockIdx.x * 128;

    const int wid = tid >> 5;
    const int lane = tid & 31;
    const int wm = wid & 3;            // 4 warps in M
    const int wn = wid >> 2;           // 2 warps in N
    const int gid = lane >> 2;         // groupID 0..7
    const int tig = lane & 3;          // thread-in-group 0..3

    // load mapping (each thread: 2 float4 of A, 2 float4 of B per k-tile)
    const int aIdx0 = tid;             // + 256
    // A element: row = idx>>2, colquad = (idx&3)*4
    // B element: row = idx>>5, colquad = (idx&31)*4

    float c[2][8][4];
#pragma unroll
    for (int mi = 0; mi < 2; mi++)
#pragma unroll
        for (int ni = 0; ni < 8; ni++)
#pragma unroll
            for (int v = 0; v < 4; v++) c[mi][ni][v] = 0.f;

    float4 aReg[2], bReg[2];

    // prologue: load k-tile 0
#pragma unroll
    for (int i = 0; i < 2; i++) {
        int idx = aIdx0 + i * 256;
        aReg[i] = *(const float4*)(A + (size_t)(m0 + (idx >> 2)) * EMB + ((idx & 3) << 2));
        bReg[i] = *(const float4*)(B + (size_t)(idx >> 5) * NDIM + n0 + ((idx & 31) << 2));
    }
    {
#pragma unroll
        for (int i = 0; i < 2; i++) {
            int idx = aIdx0 + i * 256;
            int ar = idx >> 2, ac = (idx & 3) << 2;
            As[ac + 0][ar] = f2tf32(aReg[i].x);
            As[ac + 1][ar] = f2tf32(aReg[i].y);
            As[ac + 2][ar] = f2tf32(aReg[i].z);
            As[ac + 3][ar] = f2tf32(aReg[i].w);
            int br = idx >> 5, bc = (idx & 31) << 2;
            uint4 u;
            u.x = f2tf32(bReg[i].x); u.y = f2tf32(bReg[i].y);
            u.z = f2tf32(bReg[i].z); u.w = f2tf32(bReg[i].w);
            *(uint4*)&Bs[br][bc] = u;
        }
    }
    __syncthreads();

    for (int k0 = GBK; k0 <= EMB; k0 += GBK) {
        // prefetch next k-tile into registers
        if (k0 < EMB) {
#pragma unroll
            for (int i = 0; i < 2; i++) {
                int idx = aIdx0 + i * 256;
                aReg[i] = *(const float4*)(A + (size_t)(m0 + (idx >> 2)) * EMB + k0 + ((idx & 3) << 2));
                bReg[i] = *(const float4*)(B + (size_t)(k0 + (idx >> 5)) * NDIM + n0 + ((idx & 31) << 2));
            }
        }

        // compute on current smem tile
#pragma unroll
        for (int kt = 0; kt < 2; kt++) {
            const int kk = kt * 8;
            uint32_t a[2][4];
#pragma unroll
            for (int mi = 0; mi < 2; mi++) {
                const int mb = wm * 32 + mi * 16;
                a[mi][0] = As[kk + tig][mb + gid];
                a[mi][1] = As[kk + tig][mb + gid + 8];
                a[mi][2] = As[kk + tig + 4][mb + gid];
                a[mi][3] = As[kk + tig + 4][mb + gid + 8];
            }
            uint32_t b[8][2];
#pragma unroll
            for (int ni = 0; ni < 8; ni++) {
                const int nb = wn * 64 + ni * 8;
                b[ni][0] = Bs[kk + tig][nb + gid];
                b[ni][1] = Bs[kk + tig + 4][nb + gid];
            }
#pragma unroll
            for (int mi = 0; mi < 2; mi++)
#pragma unroll
                for (int ni = 0; ni < 8; ni++)
                    mma_tf32(c[mi][ni], a[mi][0], a[mi][1], a[mi][2], a[mi][3],
                             b[ni][0], b[ni][1]);
        }
        __syncthreads();

        if (k0 < EMB) {
#pragma unroll
            for (int i = 0; i < 2; i++) {
                int idx = aIdx0 + i * 256;
                int ar = idx >> 2, ac = (idx & 3) << 2;
                As[ac + 0][ar] = f2tf32(aReg[i].x);
                As[ac + 1][ar] = f2tf32(aReg[i].y);
                As[ac + 2][ar] = f2tf32(aReg[i].z);
                As[ac + 3][ar] = f2tf32(aReg[i].w);
                int br = idx >> 5, bc = (idx & 31) << 2;
                uint4 u;
                u.x = f2tf32(bReg[i].x); u.y = f2tf32(bReg[i].y);
                u.z = f2tf32(bReg[i].z); u.w = f2tf32(bReg[i].w);
                *(uint4*)&Bs[br][bc] = u;
            }
            __syncthreads();
        }
    }

    // epilogue
#pragma unroll
    for (int mi = 0; mi < 2; mi++) {
#pragma unroll
        for (int half = 0; half < 2; half++) {
            const int m = m0 + wm * 32 + mi * 16 + gid + half * 8;
#pragma unroll
            for (int ni = 0; ni < 8; ni++) {
                const int n = n0 + wn * 64 + ni * 8 + 2 * tig;
                const float v0 = c[mi][ni][half * 2 + 0] + bias[n];
                const float v1 = c[mi][ni][half * 2 + 1] + bias[n + 1];
                if (MODE == 0) {
                    // scatter to Q/K/V [b,h,t,d]
                    const int bb = m >> 10;
                    const int t = m & 1023;
#pragma unroll
                    for (int e = 0; e < 2; e++) {
                        const int nn = n + e;
                        const float vv = e ? v1 : v0;
                        const int which = nn / EMB;
                        const int cc = nn - which * EMB;
                        const int h = cc >> 6;
                        const int d = cc & 63;
                        float* dst = (which == 0) ? g_Q : (which == 1) ? g_K : g_V;
                        dst[(((size_t)bb * NHEAD + h) * SEQ + t) * HD + d] = vv;
                    }
                } else {
                    float2 v2; v2.x = v0; v2.y = v1;
                    *(float2*)(out + (size_t)m * NDIM + n) = v2;
                }
            }
        }
    }
}

// ---------------------------------------------------------------------------
// Causal flash attention. One thread per query row; 128 rows per block.
// K/V staged in SMEM in 64-row tiles; scores processed in 16-key register
// chunks (keeps everything in registers, no dynamic-index local array).
// ---------------------------------------------------------------------------
#define TQ 128
#define TS 64
#define CH 16

__global__ __launch_bounds__(128) void attn_kernel()
{
    __shared__ float Ks[TS][HD];
    __shared__ float Vs[TS][HD];

    const int bh = blockIdx.y;                       // 0..95
    const int r = blockIdx.x * TQ + threadIdx.x;     // query row
    const float scale = 0.125f;                      // 1/sqrt(64)

    const float* Qp = g_Q + ((size_t)bh * SEQ + r) * HD;
    float q[HD];
#pragma unroll
    for (int d = 0; d < HD; d += 4) {
        float4 v4 = *(const float4*)(Qp + d);
        q[d] = v4.x; q[d + 1] = v4.y; q[d + 2] = v4.z; q[d + 3] = v4.w;
    }

    float o[HD];
#pragma unroll
    for (int d = 0; d < HD; d++) o[d] = 0.f;
    float mrow = -1e30f;
    float l = 0.f;

    const int kend = blockIdx.x * TQ + TQ;           // keys needed by this block

    const float* Kbase = g_K + (size_t)bh * SEQ * HD;
    const float* Vbase = g_V + (size_t)bh * SEQ * HD;

    for (int t0 = 0; t0 < kend; t0 += TS) {
        __syncthreads();
        const float4* Kp = (const float4*)(Kbase + (size_t)t0 * HD);
        const float4* Vp = (const float4*)(Vbase + (size_t)t0 * HD);
        float4* Kss = (float4*)&Ks[0][0];
        float4* Vss = (float4*)&Vs[0][0];
#pragma unroll
        for (int it = 0; it < 8; it++) {
            int i = threadIdx.x + it * 128;
            Kss[i] = Kp[i];
            Vss[i] = Vp[i];
        }
        __syncthreads();

        for (int c0 = 0; c0 < TS; c0 += CH) {
            if (t0 + c0 > r) break;     // fully masked chunk (and all later ones)

            float s[CH];
#pragma unroll
            for (int j = 0; j < CH; j++) {
                const float4* kr = (const float4*)&Ks[c0 + j][0];
                float a0 = 0.f, a1 = 0.f, a2 = 0.f, a3 = 0.f;
#pragma unroll
                for (int d = 0; d < HD / 4; d++) {
                    float4 kv = kr[d];
                    a0 += q[4 * d + 0] * kv.x;
                    a1 += q[4 * d + 1] * kv.y;
                    a2 += q[4 * d + 2] * kv.z;
                    a3 += q[4 * d + 3] * kv.w;
                }
                float val = (a0 + a1 + a2 + a3) * scale;
                s[j] = (t0 + c0 + j <= r) ? val : -1e30f;
            }

            float tmax = -1e30f;
#pragma unroll
            for (int j = 0; j < CH; j++) tmax = fmaxf(tmax, s[j]);
            const float mnew = fmaxf(mrow, tmax);
            const float corr = __expf(mrow - mnew);
            l *= corr;
#pragma unroll
            for (int d = 0; d < HD; d++) o[d] *= corr;
            mrow = mnew;

#pragma unroll
            for (int j = 0; j < CH; j++) {
                const float p = __expf(s[j] - mnew);
                l += p;
                const float4* vr = (const float4*)&Vs[c0 + j][0];
#pragma unroll
                for (int d = 0; d < HD / 4; d++) {
                    float4 vv = vr[d];
                    o[4 * d + 0] += p * vv.x;
                    o[4 * d + 1] += p * vv.y;
                    o[4 * d + 2] += p * vv.z;
                    o[4 * d + 3] += p * vv.w;
                }
            }
        }
    }

    // write back to [b, t, h*64 + d]
    const float inv = 1.f / l;
    const int b = bh / NHEAD;
    const int h = bh - b * NHEAD;
    float* yp = g_Y + ((size_t)(b * SEQ + r)) * EMB + h * HD;
#pragma unroll
    for (int d = 0; d < HD; d += 4) {
        float4 v4;
        v4.x = o[d] * inv; v4.y = o[d + 1] * inv;
        v4.z = o[d + 2] * inv; v4.w = o[d + 3] * inv;
        *(float4*)(yp + d) = v4;
    }
}

// ---------------------------------------------------------------------------
extern "C" void kernel_launch(void* const* d_in, const int* in_sizes, int n_in,
                              void* d_out, int out_size)
{
    const float* x      = (const float*)d_in[0];
    const float* W_attn = (const float*)d_in[1];
    const float* b_attn = (const float*)d_in[2];
    const float* W_proj = (const float*)d_in[3];
    const float* b_proj = (const float*)d_in[4];
    float* out = (float*)d_out;

    (void)in_sizes; (void)n_in; (void)out_size;

    dim3 g1(QKV_N / 128, M_ROWS / 128);    // (18, 64)
    gemm_tf32_kernel<QKV_N, 0><<<g1, 256>>>(x, W_attn, b_attn, nullptr);

    dim3 g2(SEQ / TQ, BATCH * NHEAD);      // (8, 96)
    attn_kernel<<<g2, 128>>>();

    dim3 g3(EMB / 128, M_ROWS / 128);      // (6, 64)
    gemm_tf32_kernel<EMB, 1><<<g3, 256>>>(nullptr, W_proj, b_proj, out);
}

// round 3
// speedup vs baseline: 3.5374x; 1.9717x over previous
#include <cuda_runtime.h>
#include <math.h>
#include <stdint.h>

// Problem constants
#define BATCH 8
#define SEQ   1024
#define EMB   768
#define NHEAD 12
#define HD    64
#define M_ROWS (BATCH * SEQ)        // 8192
#define QKV_N  (3 * EMB)            // 2304

// Scratch (device globals — no allocations allowed)
__device__ float g_Q[BATCH * NHEAD * SEQ * HD];   // [b,h,t,d]
__device__ float g_K[BATCH * NHEAD * SEQ * HD];
__device__ float g_V[BATCH * NHEAD * SEQ * HD];
__device__ float g_Y[M_ROWS * EMB];               // attention output, [b*t, c]

// ---------------------------------------------------------------------------
// tf32 helpers
// ---------------------------------------------------------------------------
__device__ __forceinline__ uint32_t f2tf32(float f) {
    uint32_t u;
    asm("cvt.rna.tf32.f32 %0, %1;" : "=r"(u) : "f"(f));
    return u;
}

__device__ __forceinline__ void mma_tf32(float c[4],
                                         uint32_t a0, uint32_t a1, uint32_t a2, uint32_t a3,
                                         uint32_t b0, uint32_t b1) {
    asm volatile(
        "mma.sync.aligned.m16n8k8.row.col.f32.tf32.tf32.f32 "
        "{%0,%1,%2,%3}, {%4,%5,%6,%7}, {%8,%9}, {%0,%1,%2,%3};\n"
        : "+f"(c[0]), "+f"(c[1]), "+f"(c[2]), "+f"(c[3])
        : "r"(a0), "r"(a1), "r"(a2), "r"(a3), "r"(b0), "r"(b1));
}

// ---------------------------------------------------------------------------
// tf32 tensor-core GEMM: C[M, NDIM] = A[M,768] @ B[768,NDIM] + bias
// Block tile 128x128, BK=16, 256 threads = 8 warps (warp tile 32x64).
// MODE 0: QKV — scatter into g_Q/g_K/g_V head-major.
// MODE 1: proj — A is g_Y, write out = y @ W_proj + bias.
// ---------------------------------------------------------------------------
#define GBK 16
#define SPAD 136   // 128 + 8: conflict-free fragment loads

template<int NDIM, int MODE>
__global__ __launch_bounds__(256, 2) void gemm_tf32_kernel(
    const float* __restrict__ Ain, const float* __restrict__ B,
    const float* __restrict__ bias, float* __restrict__ out)
{
    __shared__ uint32_t As[GBK][SPAD];   // [k][m]
    __shared__ uint32_t Bs[GBK][SPAD];   // [k][n]

    const float* A = (MODE == 1) ? g_Y : Ain;

    const int tid = threadIdx.x;
    const int m0 = blockIdx.y * 128;
    const int n0 = blockIdx.x * 128;

    const int wid = tid >> 5;
    const int lane = tid & 31;
    const int wm = wid & 3;            // 4 warps in M
    const int wn = wid >> 2;           // 2 warps in N
    const int gid = lane >> 2;         // groupID 0..7
    const int tig = lane & 3;          // thread-in-group 0..3

    const int aIdx0 = tid;             // + 256

    float c[2][8][4];
#pragma unroll
    for (int mi = 0; mi < 2; mi++)
#pragma unroll
        for (int ni = 0; ni < 8; ni++)
#pragma unroll
            for (int v = 0; v < 4; v++) c[mi][ni][v] = 0.f;

    float4 aReg[2], bReg[2];

    // prologue: load k-tile 0
#pragma unroll
    for (int i = 0; i < 2; i++) {
        int idx = aIdx0 + i * 256;
        aReg[i] = *(const float4*)(A + (size_t)(m0 + (idx >> 2)) * EMB + ((idx & 3) << 2));
        bReg[i] = *(const float4*)(B + (size_t)(idx >> 5) * NDIM + n0 + ((idx & 31) << 2));
    }
    {
#pragma unroll
        for (int i = 0; i < 2; i++) {
            int idx = aIdx0 + i * 256;
            int ar = idx >> 2, ac = (idx & 3) << 2;
            As[ac + 0][ar] = f2tf32(aReg[i].x);
            As[ac + 1][ar] = f2tf32(aReg[i].y);
            As[ac + 2][ar] = f2tf32(aReg[i].z);
            As[ac + 3][ar] = f2tf32(aReg[i].w);
            int br = idx >> 5, bc = (idx & 31) << 2;
            uint4 u;
            u.x = f2tf32(bReg[i].x); u.y = f2tf32(bReg[i].y);
            u.z = f2tf32(bReg[i].z); u.w = f2tf32(bReg[i].w);
            *(uint4*)&Bs[br][bc] = u;
        }
    }
    __syncthreads();

    for (int k0 = GBK; k0 <= EMB; k0 += GBK) {
        // prefetch next k-tile into registers
        if (k0 < EMB) {
#pragma unroll
            for (int i = 0; i < 2; i++) {
                int idx = aIdx0 + i * 256;
                aReg[i] = *(const float4*)(A + (size_t)(m0 + (idx >> 2)) * EMB + k0 + ((idx & 3) << 2));
                bReg[i] = *(const float4*)(B + (size_t)(k0 + (idx >> 5)) * NDIM + n0 + ((idx & 31) << 2));
            }
        }

        // compute on current smem tile
#pragma unroll
        for (int kt = 0; kt < 2; kt++) {
            const int kk = kt * 8;
            uint32_t a[2][4];
#pragma unroll
            for (int mi = 0; mi < 2; mi++) {
                const int mb = wm * 32 + mi * 16;
                a[mi][0] = As[kk + tig][mb + gid];
                a[mi][1] = As[kk + tig][mb + gid + 8];
                a[mi][2] = As[kk + tig + 4][mb + gid];
                a[mi][3] = As[kk + tig + 4][mb + gid + 8];
            }
            uint32_t b[8][2];
#pragma unroll
            for (int ni = 0; ni < 8; ni++) {
                const int nb = wn * 64 + ni * 8;
                b[ni][0] = Bs[kk + tig][nb + gid];
                b[ni][1] = Bs[kk + tig + 4][nb + gid];
            }
#pragma unroll
            for (int mi = 0; mi < 2; mi++)
#pragma unroll
                for (int ni = 0; ni < 8; ni++)
                    mma_tf32(c[mi][ni], a[mi][0], a[mi][1], a[mi][2], a[mi][3],
                             b[ni][0], b[ni][1]);
        }
        __syncthreads();

        if (k0 < EMB) {
#pragma unroll
            for (int i = 0; i < 2; i++) {
                int idx = aIdx0 + i * 256;
                int ar = idx >> 2, ac = (idx & 3) << 2;
                As[ac + 0][ar] = f2tf32(aReg[i].x);
                As[ac + 1][ar] = f2tf32(aReg[i].y);
                As[ac + 2][ar] = f2tf32(aReg[i].z);
                As[ac + 3][ar] = f2tf32(aReg[i].w);
                int br = idx >> 5, bc = (idx & 31) << 2;
                uint4 u;
                u.x = f2tf32(bReg[i].x); u.y = f2tf32(bReg[i].y);
                u.z = f2tf32(bReg[i].z); u.w = f2tf32(bReg[i].w);
                *(uint4*)&Bs[br][bc] = u;
            }
            __syncthreads();
        }
    }

    // epilogue
#pragma unroll
    for (int mi = 0; mi < 2; mi++) {
#pragma unroll
        for (int half = 0; half < 2; half++) {
            const int m = m0 + wm * 32 + mi * 16 + gid + half * 8;
#pragma unroll
            for (int ni = 0; ni < 8; ni++) {
                const int n = n0 + wn * 64 + ni * 8 + 2 * tig;
                const float v0 = c[mi][ni][half * 2 + 0] + bias[n];
                const float v1 = c[mi][ni][half * 2 + 1] + bias[n + 1];
                if (MODE == 0) {
                    const int bb = m >> 10;
                    const int t = m & 1023;
#pragma unroll
                    for (int e = 0; e < 2; e++) {
                        const int nn = n + e;
                        const float vv = e ? v1 : v0;
                        const int which = nn / EMB;
                        const int cc = nn - which * EMB;
                        const int h = cc >> 6;
                        const int d = cc & 63;
                        float* dst = (which == 0) ? g_Q : (which == 1) ? g_K : g_V;
                        dst[(((size_t)bb * NHEAD + h) * SEQ + t) * HD + d] = vv;
                    }
                } else {
                    float2 v2; v2.x = v0; v2.y = v1;
                    *(float2*)(out + (size_t)m * NDIM + n) = v2;
                }
            }
        }
    }
}

// ---------------------------------------------------------------------------
// Tensor-core causal flash attention (tf32 m16n8k8).
// Block: 128 threads = 4 warps; 64 query rows (16 per warp); 64-key tiles.
// K and V share one smem buffer (phased); P goes through smem for layout fix.
// ---------------------------------------------------------------------------
#define ASTR 68   // smem row stride (floats): addr%32 = 4*gid+tig -> conflict-free

__global__ __launch_bounds__(128) void attn_mma_kernel()
{
    __shared__ uint32_t KVs[64 * ASTR];   // K tile, then V tile ([key][d], tf32)
    __shared__ uint32_t Ps[64 * ASTR];    // Q staging, then P tiles ([row][col], tf32)

    const int bh = blockIdx.y;
    const int q0 = blockIdx.x * 64;
    const int tid = threadIdx.x;
    const int wid = tid >> 5;
    const int lane = tid & 31;
    const int gid = lane >> 2;
    const int tig = lane & 3;
    const int w16 = wid * 16;

    const float* Qbase = g_Q + (size_t)bh * SEQ * HD;
    const float* Kbase = g_K + (size_t)bh * SEQ * HD;
    const float* Vbase = g_V + (size_t)bh * SEQ * HD;

    // ---- stage Q tile (scaled) into Ps, read A-fragments into registers ----
#pragma unroll
    for (int i = 0; i < 8; i++) {
        int idx = tid + i * 128;                 // 1024 float4
        int r = idx >> 4, dq = (idx & 15) << 2;
        float4 v = *(const float4*)(Qbase + (size_t)(q0 + r) * HD + dq);
        uint32_t* dst = &Ps[r * ASTR + dq];
        dst[0] = f2tf32(v.x * 0.125f);
        dst[1] = f2tf32(v.y * 0.125f);
        dst[2] = f2tf32(v.z * 0.125f);
        dst[3] = f2tf32(v.w * 0.125f);
    }
    __syncthreads();

    uint32_t qa[8][4];
#pragma unroll
    for (int kk = 0; kk < 8; kk++) {
        qa[kk][0] = Ps[(w16 + gid) * ASTR + 8 * kk + tig];
        qa[kk][1] = Ps[(w16 + gid + 8) * ASTR + 8 * kk + tig];
        qa[kk][2] = Ps[(w16 + gid) * ASTR + 8 * kk + tig + 4];
        qa[kk][3] = Ps[(w16 + gid + 8) * ASTR + 8 * kk + tig + 4];
    }

    float o[8][4];
#pragma unroll
    for (int ni = 0; ni < 8; ni++)
#pragma unroll
        for (int v = 0; v < 4; v++) o[ni][v] = 0.f;
    float m0 = -1e30f, m1 = -1e30f, l0 = 0.f, l1 = 0.f;

    for (int t0 = 0; t0 <= q0; t0 += 64) {
        __syncthreads();   // prev iter's PV reads of KVs/Ps complete (covers Q frag reads on iter 0)

        // ---- stage K tile [key][d] as tf32 ----
#pragma unroll
        for (int i = 0; i < 8; i++) {
            int idx = tid + i * 128;
            int r = idx >> 4, dq = (idx & 15) << 2;
            float4 v = *(const float4*)(Kbase + (size_t)(t0 + r) * HD + dq);
            uint32_t* dst = &KVs[r * ASTR + dq];
            dst[0] = f2tf32(v.x); dst[1] = f2tf32(v.y);
            dst[2] = f2tf32(v.z); dst[3] = f2tf32(v.w);
        }
        __syncthreads();

        // ---- issue V loads early (gmem -> regs), hidden under S phase ----
        float4 vreg[8];
#pragma unroll
        for (int i = 0; i < 8; i++) {
            int idx = tid + i * 128;
            vreg[i] = *(const float4*)(Vbase + (size_t)(t0 + (idx >> 4)) * HD + ((idx & 15) << 2));
        }

        // ---- S = (Q*scale) @ K^T ----
        float s[8][4];
#pragma unroll
        for (int ni = 0; ni < 8; ni++)
#pragma unroll
            for (int v = 0; v < 4; v++) s[ni][v] = 0.f;

#pragma unroll
        for (int kk = 0; kk < 8; kk++) {
#pragma unroll
            for (int ni = 0; ni < 8; ni++) {
                uint32_t b0 = KVs[(8 * ni + gid) * ASTR + 8 * kk + tig];
                uint32_t b1 = KVs[(8 * ni + gid) * ASTR + 8 * kk + tig + 4];
                mma_tf32(s[ni], qa[kk][0], qa[kk][1], qa[kk][2], qa[kk][3], b0, b1);
            }
        }

        // ---- causal mask (diagonal tile only) ----
        if (t0 == q0) {
            const int r0 = w16 + gid, r1 = r0 + 8;
#pragma unroll
            for (int ni = 0; ni < 8; ni++) {
                const int key0 = 8 * ni + 2 * tig;
                if (key0 > r0)     s[ni][0] = -1e30f;
                if (key0 + 1 > r0) s[ni][1] = -1e30f;
                if (key0 > r1)     s[ni][2] = -1e30f;
                if (key0 + 1 > r1) s[ni][3] = -1e30f;
            }
        }

        // ---- online softmax (s -> p in place) ----
        float rmax0 = -1e30f, rmax1 = -1e30f;
#pragma unroll
        for (int ni = 0; ni < 8; ni++) {
            rmax0 = fmaxf(rmax0, fmaxf(s[ni][0], s[ni][1]));
            rmax1 = fmaxf(rmax1, fmaxf(s[ni][2], s[ni][3]));
        }
        rmax0 = fmaxf(rmax0, __shfl_xor_sync(0xffffffffu, rmax0, 1));
        rmax0 = fmaxf(rmax0, __shfl_xor_sync(0xffffffffu, rmax0, 2));
        rmax1 = fmaxf(rmax1, __shfl_xor_sync(0xffffffffu, rmax1, 1));
        rmax1 = fmaxf(rmax1, __shfl_xor_sync(0xffffffffu, rmax1, 2));

        const float mn0 = fmaxf(m0, rmax0);
        const float mn1 = fmaxf(m1, rmax1);
        const float cr0 = __expf(m0 - mn0);
        const float cr1 = __expf(m1 - mn1);
        m0 = mn0; m1 = mn1;

        float sum0 = 0.f, sum1 = 0.f;
#pragma unroll
        for (int ni = 0; ni < 8; ni++) {
            s[ni][0] = __expf(s[ni][0] - m0);
            s[ni][1] = __expf(s[ni][1] - m0);
            s[ni][2] = __expf(s[ni][2] - m1);
            s[ni][3] = __expf(s[ni][3] - m1);
            sum0 += s[ni][0] + s[ni][1];
            sum1 += s[ni][2] + s[ni][3];
            o[ni][0] *= cr0; o[ni][1] *= cr0;
            o[ni][2] *= cr1; o[ni][3] *= cr1;
        }
        sum0 += __shfl_xor_sync(0xffffffffu, sum0, 1);
        sum0 += __shfl_xor_sync(0xffffffffu, sum0, 2);
        sum1 += __shfl_xor_sync(0xffffffffu, sum1, 1);
        sum1 += __shfl_xor_sync(0xffffffffu, sum1, 2);
        l0 = l0 * cr0 + sum0;
        l1 = l1 * cr1 + sum1;

        __syncthreads();   // all warps done reading K from KVs

        // ---- stage V tile into KVs, P tile into Ps (both tf32) ----
#pragma unroll
        for (int i = 0; i < 8; i++) {
            int idx = tid + i * 128;
            int r = idx >> 4, dq = (idx & 15) << 2;
            uint32_t* dst = &KVs[r * ASTR + dq];
            dst[0] = f2tf32(vreg[i].x); dst[1] = f2tf32(vreg[i].y);
            dst[2] = f2tf32(vreg[i].z); dst[3] = f2tf32(vreg[i].w);
        }
#pragma unroll
        for (int ni = 0; ni < 8; ni++) {
            uint32_t* d0 = &Ps[(w16 + gid) * ASTR + 8 * ni + 2 * tig];
            d0[0] = f2tf32(s[ni][0]); d0[1] = f2tf32(s[ni][1]);
            uint32_t* d1 = &Ps[(w16 + gid + 8) * ASTR + 8 * ni + 2 * tig];
            d1[0] = f2tf32(s[ni][2]); d1[1] = f2tf32(s[ni][3]);
        }
        __syncthreads();

        // ---- O += P @ V ----
#pragma unroll
        for (int kk = 0; kk < 8; kk++) {
            uint32_t pa0 = Ps[(w16 + gid) * ASTR + 8 * kk + tig];
            uint32_t pa1 = Ps[(w16 + gid + 8) * ASTR + 8 * kk + tig];
            uint32_t pa2 = Ps[(w16 + gid) * ASTR + 8 * kk + tig + 4];
            uint32_t pa3 = Ps[(w16 + gid + 8) * ASTR + 8 * kk + tig + 4];
#pragma unroll
            for (int ni = 0; ni < 8; ni++) {
                uint32_t b0 = KVs[(8 * kk + tig) * ASTR + 8 * ni + gid];
                uint32_t b1 = KVs[(8 * kk + tig + 4) * ASTR + 8 * ni + gid];
                mma_tf32(o[ni], pa0, pa1, pa2, pa3, b0, b1);
            }
        }
    }

    // ---- writeback: y[b, t, h*64+d] ----
    const float inv0 = 1.f / l0;
    const float inv1 = 1.f / l1;
    const int b = bh / NHEAD;
    const int h = bh - b * NHEAD;
    float* Yb = g_Y + ((size_t)(b * SEQ + q0 + w16 + gid)) * EMB + h * HD;
#pragma unroll
    for (int ni = 0; ni < 8; ni++) {
        float2 v0; v0.x = o[ni][0] * inv0; v0.y = o[ni][1] * inv0;
        *(float2*)(Yb + 8 * ni + 2 * tig) = v0;
        float2 v1; v1.x = o[ni][2] * inv1; v1.y = o[ni][3] * inv1;
        *(float2*)(Yb + (size_t)8 * EMB + 8 * ni + 2 * tig) = v1;
    }
}

// ---------------------------------------------------------------------------
extern "C" void kernel_launch(void* const* d_in, const int* in_sizes, int n_in,
                              void* d_out, int out_size)
{
    const float* x      = (const float*)d_in[0];
    const float* W_attn = (const float*)d_in[1];
    const float* b_attn = (const float*)d_in[2];
    const float* W_proj = (const float*)d_in[3];
    const float* b_proj = (const float*)d_in[4];
    float* out = (float*)d_out;

    (void)in_sizes; (void)n_in; (void)out_size;

    dim3 g1(QKV_N / 128, M_ROWS / 128);    // (18, 64)
    gemm_tf32_kernel<QKV_N, 0><<<g1, 256>>>(x, W_attn, b_attn, nullptr);

    dim3 g2(SEQ / 64, BATCH * NHEAD);      // (16, 96)
    attn_mma_kernel<<<g2, 128>>>();

    dim3 g3(EMB / 128, M_ROWS / 128);      // (6, 64)
    gemm_tf32_kernel<EMB, 1><<<g3, 256>>>(nullptr, W_proj, b_proj, out);
}

// round 10
// speedup vs baseline: 3.6095x; 1.0204x over previous
#include <cuda_runtime.h>
#include <math.h>
#include <stdint.h>

// Problem constants
#define BATCH 8
#define SEQ   1024
#define EMB   768
#define NHEAD 12
#define HD    64
#define M_ROWS (BATCH * SEQ)        // 8192
#define QKV_N  (3 * EMB)            // 2304

// Scratch (device globals — no allocations allowed)
__device__ float g_Q[BATCH * NHEAD * SEQ * HD];   // [b,h,t,d] fp32
__device__ float g_K[BATCH * NHEAD * SEQ * HD];
__device__ float g_V[BATCH * NHEAD * SEQ * HD];
__device__ float g_Y[M_ROWS * EMB];               // attention out (tf32-rounded)
__device__ float g_Xc[M_ROWS * EMB];              // x, tf32-rounded
__device__ float g_Wa[EMB * QKV_N];               // W_attn, tf32-rounded (same layout)
__device__ float g_Wp[EMB * EMB];                 // W_proj, tf32-rounded

// ---------------------------------------------------------------------------
// helpers
// ---------------------------------------------------------------------------
__device__ __forceinline__ uint32_t f2tf32(float f) {
    uint32_t u;
    asm("cvt.rna.tf32.f32 %0, %1;" : "=r"(u) : "f"(f));
    return u;
}
__device__ __forceinline__ float f2tf32f(float f) {
    return __uint_as_float(f2tf32(f));
}

__device__ __forceinline__ void mma_tf32(float c[4],
                                         uint32_t a0, uint32_t a1, uint32_t a2, uint32_t a3,
                                         uint32_t b0, uint32_t b1) {
    asm volatile(
        "mma.sync.aligned.m16n8k8.row.col.f32.tf32.tf32.f32 "
        "{%0,%1,%2,%3}, {%4,%5,%6,%7}, {%8,%9}, {%0,%1,%2,%3};\n"
        : "+f"(c[0]), "+f"(c[1]), "+f"(c[2]), "+f"(c[3])
        : "r"(a0), "r"(a1), "r"(a2), "r"(a3), "r"(b0), "r"(b1));
}

// ---------------------------------------------------------------------------
// Pre-pass: element-wise tf32 rounding. Destination global chosen INSIDE the
// kernel (never pass a __device__ symbol from host — that was the R6/R8 bug).
// ---------------------------------------------------------------------------
template<int WHICH>   // 0 -> g_Xc, 1 -> g_Wa, 2 -> g_Wp
__global__ __launch_bounds__(256) void cvt_tf32_kernel(
    const float* __restrict__ in, int n4)
{
    float* __restrict__ out = (WHICH == 0) ? g_Xc : (WHICH == 1) ? g_Wa : g_Wp;
    const int i = blockIdx.x * 256 + threadIdx.x;
    if (i < n4) {
        float4 v = ((const float4*)in)[i];
        v.x = f2tf32f(v.x); v.y = f2tf32f(v.y);
        v.z = f2tf32f(v.z); v.w = f2tf32f(v.w);
        ((float4*)out)[i] = v;
    }
}

// ---------------------------------------------------------------------------
// Double-buffered tf32 GEMM: C[M, NDIM] = A[M,768] @ B[768,NDIM] + bias
// Operands pre-rounded to tf32 (no cvt in loop). Block tile 128x128, BK=16,
// 256 threads = 8 warps (warp tile 32x64). Consumer identical to R3.
// MODE 0: QKV — scatter into g_Q/g_K/g_V. MODE 1: proj — g_Y -> out.
// ---------------------------------------------------------------------------
#define GBK 16
#define SPAD 136   // 128 + 8: conflict-free fragment loads
#define KTILES 48

template<int NDIM, int MODE>
__global__ __launch_bounds__(256, 2) void gemm_db_kernel(
    const float* __restrict__ bias, float* __restrict__ out)
{
    __shared__ float As[2][GBK][SPAD];   // [buf][k][m]
    __shared__ float Bs[2][GBK][SPAD];   // [buf][k][n]

    const float* __restrict__ A = (MODE == 1) ? g_Y : g_Xc;
    const float* __restrict__ B = (MODE == 0) ? g_Wa : g_Wp;

    const int tid = threadIdx.x;
    const int m0 = blockIdx.y * 128;
    const int n0 = blockIdx.x * 128;

    const int wid = tid >> 5;
    const int lane = tid & 31;
    const int wm = wid & 3;            // 4 warps in M
    const int wn = wid >> 2;           // 2 warps in N
    const int gid = lane >> 2;
    const int tig = lane & 3;

    float c[2][8][4];
#pragma unroll
    for (int mi = 0; mi < 2; mi++)
#pragma unroll
        for (int ni = 0; ni < 8; ni++)
#pragma unroll
            for (int v = 0; v < 4; v++) c[mi][ni][v] = 0.f;

    float4 aReg[2], bReg[2];

    // ---- prologue: tile 0 -> buf 0 ----
#pragma unroll
    for (int i = 0; i < 2; i++) {
        const int idx = tid + i * 256;
        aReg[i] = *(const float4*)(A + (size_t)(m0 + (idx >> 2)) * EMB + ((idx & 3) << 2));
        bReg[i] = *(const float4*)(B + (size_t)(idx >> 5) * NDIM + n0 + ((idx & 31) << 2));
    }
#pragma unroll
    for (int i = 0; i < 2; i++) {
        const int idx = tid + i * 256;
        const int ar = idx >> 2, ac = (idx & 3) << 2;
        As[0][ac + 0][ar] = aReg[i].x;
        As[0][ac + 1][ar] = aReg[i].y;
        As[0][ac + 2][ar] = aReg[i].z;
        As[0][ac + 3][ar] = aReg[i].w;
        const int br = idx >> 5, bc = (idx & 31) << 2;
        *(float4*)&Bs[0][br][bc] = bReg[i];
    }
    __syncthreads();

    for (int t = 0; t < KTILES; t++) {
        const int buf = t & 1;

        // prefetch next tile into registers
        if (t + 1 < KTILES) {
            const int k0 = (t + 1) * GBK;
#pragma unroll
            for (int i = 0; i < 2; i++) {
                const int idx = tid + i * 256;
                aReg[i] = *(const float4*)(A + (size_t)(m0 + (idx >> 2)) * EMB + k0 + ((idx & 3) << 2));
                bReg[i] = *(const float4*)(B + (size_t)(k0 + (idx >> 5)) * NDIM + n0 + ((idx & 31) << 2));
            }
        }

        // compute on current buffer
#pragma unroll
        for (int kt = 0; kt < 2; kt++) {
            const int kk = kt * 8;
            float a[2][4];
#pragma unroll
            for (int mi = 0; mi < 2; mi++) {
                const int mb = wm * 32 + mi * 16;
                a[mi][0] = As[buf][kk + tig][mb + gid];
                a[mi][1] = As[buf][kk + tig][mb + gid + 8];
                a[mi][2] = As[buf][kk + tig + 4][mb + gid];
                a[mi][3] = As[buf][kk + tig + 4][mb + gid + 8];
            }
            float b[8][2];
#pragma unroll
            for (int ni = 0; ni < 8; ni++) {
                const int nb = wn * 64 + ni * 8;
                b[ni][0] = Bs[buf][kk + tig][nb + gid];
                b[ni][1] = Bs[buf][kk + tig + 4][nb + gid];
            }
#pragma unroll
            for (int mi = 0; mi < 2; mi++)
#pragma unroll
                for (int ni = 0; ni < 8; ni++)
                    mma_tf32(c[mi][ni],
                             __float_as_uint(a[mi][0]), __float_as_uint(a[mi][1]),
                             __float_as_uint(a[mi][2]), __float_as_uint(a[mi][3]),
                             __float_as_uint(b[ni][0]), __float_as_uint(b[ni][1]));
        }

        // store prefetched tile into the other buffer
        if (t + 1 < KTILES) {
            const int nb2 = buf ^ 1;
#pragma unroll
            for (int i = 0; i < 2; i++) {
                const int idx = tid + i * 256;
                const int ar = idx >> 2, ac = (idx & 3) << 2;
                As[nb2][ac + 0][ar] = aReg[i].x;
                As[nb2][ac + 1][ar] = aReg[i].y;
                As[nb2][ac + 2][ar] = aReg[i].z;
                As[nb2][ac + 3][ar] = aReg[i].w;
                const int br = idx >> 5, bc = (idx & 31) << 2;
                *(float4*)&Bs[nb2][br][bc] = bReg[i];
            }
            __syncthreads();
        }
    }

    // epilogue (identical to R2/R3)
#pragma unroll
    for (int mi = 0; mi < 2; mi++) {
#pragma unroll
        for (int half = 0; half < 2; half++) {
            const int m = m0 + wm * 32 + mi * 16 + gid + half * 8;
#pragma unroll
            for (int ni = 0; ni < 8; ni++) {
                const int n = n0 + wn * 64 + ni * 8 + 2 * tig;
                const float v0 = c[mi][ni][half * 2 + 0] + bias[n];
                const float v1 = c[mi][ni][half * 2 + 1] + bias[n + 1];
                if (MODE == 0) {
                    const int bb = m >> 10;
                    const int t = m & 1023;
#pragma unroll
                    for (int e = 0; e < 2; e++) {
                        const int nn = n + e;
                        const float vv = e ? v1 : v0;
                        const int which = nn / EMB;
                        const int cc = nn - which * EMB;
                        const int h = cc >> 6;
                        const int d = cc & 63;
                        float* dst = (which == 0) ? g_Q : (which == 1) ? g_K : g_V;
                        dst[(((size_t)bb * NHEAD + h) * SEQ + t) * HD + d] = vv;
                    }
                } else {
                    float2 v2; v2.x = v0; v2.y = v1;
                    *(float2*)(out + (size_t)m * NDIM + n) = v2;
                }
            }
        }
    }
}

// ---------------------------------------------------------------------------
// Tensor-core causal flash attention (tf32 m16n8k8) — identical to R3 except
// the final writeback rounds to tf32 (so the proj GEMM needs no cvt).
// ---------------------------------------------------------------------------
#define ASTR 68

__global__ __launch_bounds__(128) void attn_mma_kernel()
{
    __shared__ uint32_t KVs[64 * ASTR];
    __shared__ uint32_t Ps[64 * ASTR];

    const int bh = blockIdx.y;
    const int q0 = blockIdx.x * 64;
    const int tid = threadIdx.x;
    const int wid = tid >> 5;
    const int lane = tid & 31;
    const int gid = lane >> 2;
    const int tig = lane & 3;
    const int w16 = wid * 16;

    const float* Qbase = g_Q + (size_t)bh * SEQ * HD;
    const float* Kbase = g_K + (size_t)bh * SEQ * HD;
    const float* Vbase = g_V + (size_t)bh * SEQ * HD;

#pragma unroll
    for (int i = 0; i < 8; i++) {
        int idx = tid + i * 128;
        int r = idx >> 4, dq = (idx & 15) << 2;
        float4 v = *(const float4*)(Qbase + (size_t)(q0 + r) * HD + dq);
        uint32_t* dst = &Ps[r * ASTR + dq];
        dst[0] = f2tf32(v.x * 0.125f);
        dst[1] = f2tf32(v.y * 0.125f);
        dst[2] = f2tf32(v.z * 0.125f);
        dst[3] = f2tf32(v.w * 0.125f);
    }
    __syncthreads();

    uint32_t qa[8][4];
#pragma unroll
    for (int kk = 0; kk < 8; kk++) {
        qa[kk][0] = Ps[(w16 + gid) * ASTR + 8 * kk + tig];
        qa[kk][1] = Ps[(w16 + gid + 8) * ASTR + 8 * kk + tig];
        qa[kk][2] = Ps[(w16 + gid) * ASTR + 8 * kk + tig + 4];
        qa[kk][3] = Ps[(w16 + gid + 8) * ASTR + 8 * kk + tig + 4];
    }

    float o[8][4];
#pragma unroll
    for (int ni = 0; ni < 8; ni++)
#pragma unroll
        for (int v = 0; v < 4; v++) o[ni][v] = 0.f;
    float m0 = -1e30f, m1 = -1e30f, l0 = 0.f, l1 = 0.f;

    for (int t0 = 0; t0 <= q0; t0 += 64) {
        __syncthreads();

#pragma unroll
        for (int i = 0; i < 8; i++) {
            int idx = tid + i * 128;
            int r = idx >> 4, dq = (idx & 15) << 2;
            float4 v = *(const float4*)(Kbase + (size_t)(t0 + r) * HD + dq);
            uint32_t* dst = &KVs[r * ASTR + dq];
            dst[0] = f2tf32(v.x); dst[1] = f2tf32(v.y);
            dst[2] = f2tf32(v.z); dst[3] = f2tf32(v.w);
        }
        __syncthreads();

        float4 vreg[8];
#pragma unroll
        for (int i = 0; i < 8; i++) {
            int idx = tid + i * 128;
            vreg[i] = *(const float4*)(Vbase + (size_t)(t0 + (idx >> 4)) * HD + ((idx & 15) << 2));
        }

        float s[8][4];
#pragma unroll
        for (int ni = 0; ni < 8; ni++)
#pragma unroll
            for (int v = 0; v < 4; v++) s[ni][v] = 0.f;

#pragma unroll
        for (int kk = 0; kk < 8; kk++) {
#pragma unroll
            for (int ni = 0; ni < 8; ni++) {
                uint32_t b0 = KVs[(8 * ni + gid) * ASTR + 8 * kk + tig];
                uint32_t b1 = KVs[(8 * ni + gid) * ASTR + 8 * kk + tig + 4];
                mma_tf32(s[ni], qa[kk][0], qa[kk][1], qa[kk][2], qa[kk][3], b0, b1);
            }
        }

        if (t0 == q0) {
            const int r0 = w16 + gid, r1 = r0 + 8;
#pragma unroll
            for (int ni = 0; ni < 8; ni++) {
                const int key0 = 8 * ni + 2 * tig;
                if (key0 > r0)     s[ni][0] = -1e30f;
                if (key0 + 1 > r0) s[ni][1] = -1e30f;
                if (key0 > r1)     s[ni][2] = -1e30f;
                if (key0 + 1 > r1) s[ni][3] = -1e30f;
            }
        }

        float rmax0 = -1e30f, rmax1 = -1e30f;
#pragma unroll
        for (int ni = 0; ni < 8; ni++) {
            rmax0 = fmaxf(rmax0, fmaxf(s[ni][0], s[ni][1]));
            rmax1 = fmaxf(rmax1, fmaxf(s[ni][2], s[ni][3]));
        }
        rmax0 = fmaxf(rmax0, __shfl_xor_sync(0xffffffffu, rmax0, 1));
        rmax0 = fmaxf(rmax0, __shfl_xor_sync(0xffffffffu, rmax0, 2));
        rmax1 = fmaxf(rmax1, __shfl_xor_sync(0xffffffffu, rmax1, 1));
        rmax1 = fmaxf(rmax1, __shfl_xor_sync(0xffffffffu, rmax1, 2));

        const float mn0 = fmaxf(m0, rmax0);
        const float mn1 = fmaxf(m1, rmax1);
        const float cr0 = __expf(m0 - mn0);
        const float cr1 = __expf(m1 - mn1);
        m0 = mn0; m1 = mn1;

        float sum0 = 0.f, sum1 = 0.f;
#pragma unroll
        for (int ni = 0; ni < 8; ni++) {
            s[ni][0] = __expf(s[ni][0] - m0);
            s[ni][1] = __expf(s[ni][1] - m0);
            s[ni][2] = __expf(s[ni][2] - m1);
            s[ni][3] = __expf(s[ni][3] - m1);
            sum0 += s[ni][0] + s[ni][1];
            sum1 += s[ni][2] + s[ni][3];
            o[ni][0] *= cr0; o[ni][1] *= cr0;
            o[ni][2] *= cr1; o[ni][3] *= cr1;
        }
        sum0 += __shfl_xor_sync(0xffffffffu, sum0, 1);
        sum0 += __shfl_xor_sync(0xffffffffu, sum0, 2);
        sum1 += __shfl_xor_sync(0xffffffffu, sum1, 1);
        sum1 += __shfl_xor_sync(0xffffffffu, sum1, 2);
        l0 = l0 * cr0 + sum0;
        l1 = l1 * cr1 + sum1;

        __syncthreads();

#pragma unroll
        for (int i = 0; i < 8; i++) {
            int idx = tid + i * 128;
            int r = idx >> 4, dq = (idx & 15) << 2;
            uint32_t* dst = &KVs[r * ASTR + dq];
            dst[0] = f2tf32(vreg[i].x); dst[1] = f2tf32(vreg[i].y);
            dst[2] = f2tf32(vreg[i].z); dst[3] = f2tf32(vreg[i].w);
        }
#pragma unroll
        for (int ni = 0; ni < 8; ni++) {
            uint32_t* d0 = &Ps[(w16 + gid) * ASTR + 8 * ni + 2 * tig];
            d0[0] = f2tf32(s[ni][0]); d0[1] = f2tf32(s[ni][1]);
            uint32_t* d1 = &Ps[(w16 + gid + 8) * ASTR + 8 * ni + 2 * tig];
            d1[0] = f2tf32(s[ni][2]); d1[1] = f2tf32(s[ni][3]);
        }
        __syncthreads();

#pragma unroll
        for (int kk = 0; kk < 8; kk++) {
            uint32_t pa0 = Ps[(w16 + gid) * ASTR + 8 * kk + tig];
            uint32_t pa1 = Ps[(w16 + gid + 8) * ASTR + 8 * kk + tig];
            uint32_t pa2 = Ps[(w16 + gid) * ASTR + 8 * kk + tig + 4];
            uint32_t pa3 = Ps[(w16 + gid + 8) * ASTR + 8 * kk + tig + 4];
#pragma unroll
            for (int ni = 0; ni < 8; ni++) {
                uint32_t b0 = KVs[(8 * kk + tig) * ASTR + 8 * ni + gid];
                uint32_t b1 = KVs[(8 * kk + tig + 4) * ASTR + 8 * ni + gid];
                mma_tf32(o[ni], pa0, pa1, pa2, pa3, b0, b1);
            }
        }
    }

    // writeback (tf32-rounded so proj GEMM consumes without cvt)
    const float inv0 = 1.f / l0;
    const float inv1 = 1.f / l1;
    const int b = bh / NHEAD;
    const int h = bh - b * NHEAD;
    float* Yb = g_Y + ((size_t)(b * SEQ + q0 + w16 + gid)) * EMB + h * HD;
#pragma unroll
    for (int ni = 0; ni < 8; ni++) {
        float2 v0;
        v0.x = f2tf32f(o[ni][0] * inv0); v0.y = f2tf32f(o[ni][1] * inv0);
        *(float2*)(Yb + 8 * ni + 2 * tig) = v0;
        float2 v1;
        v1.x = f2tf32f(o[ni][2] * inv1); v1.y = f2tf32f(o[ni][3] * inv1);
        *(float2*)(Yb + (size_t)8 * EMB + 8 * ni + 2 * tig) = v1;
    }
}

// ---------------------------------------------------------------------------
extern "C" void kernel_launch(void* const* d_in, const int* in_sizes, int n_in,
                              void* d_out, int out_size)
{
    const float* x      = (const float*)d_in[0];
    const float* W_attn = (const float*)d_in[1];
    const float* b_attn = (const float*)d_in[2];
    const float* W_proj = (const float*)d_in[3];
    const float* b_proj = (const float*)d_in[4];
    float* out = (float*)d_out;

    (void)in_sizes; (void)n_in; (void)out_size;

    // pre-pass: tf32-round operands (destination globals selected in-kernel)
    cvt_tf32_kernel<0><<<(M_ROWS * EMB / 4 + 255) / 256, 256>>>(x, M_ROWS * EMB / 4);
    cvt_tf32_kernel<1><<<(EMB * QKV_N / 4 + 255) / 256, 256>>>(W_attn, EMB * QKV_N / 4);
    cvt_tf32_kernel<2><<<(EMB * EMB / 4 + 255) / 256, 256>>>(W_proj, EMB * EMB / 4);

    dim3 g1(QKV_N / 128, M_ROWS / 128);    // (18, 64)
    gemm_db_kernel<QKV_N, 0><<<g1, 256>>>(b_attn, nullptr);

    dim3 g2(SEQ / 64, BATCH * NHEAD);      // (16, 96)
    attn_mma_kernel<<<g2, 128>>>();

    dim3 g3(EMB / 128, M_ROWS / 128);      // (6, 64)
    gemm_db_kernel<EMB, 1><<<g3, 256>>>(b_proj, out);
}